// round 12
// baseline (speedup 1.0000x reference)
#include <cuda_runtime.h>
#include <math.h>

// HardNegativeContrastiveLoss, B=8192, D=128, T=0.1, margin=0.5.
//
// Identity (R3): the reference leaves the diagonal of neg_sim unmasked, so
// hardest_neg[i] == 1/T exactly for any input. The O(B^2 D) GEMM vanishes:
//   loss = (1/B) * sum_i relu(10.5 - dot(z1_i,z2_i)/(||z1_i||*||z2_i||))
//
// R8: R7 fixed occupancy but the single-address atomic-counter tail (1024
// serialized L2 RMWs + per-block gpu fences) dominated. Same 8192 warps,
// but 256 blocks x 1024 threads -> 4x fewer atomics/fences in the tail.

#define BB       8192
#define DD       128
#define THREADS  1024
#define NWARPS   (THREADS / 32)   // 32 warps/block
#define NBLK     256              // 256 * 32 = 8192 rows, one per warp

__device__ float    g_partials[NBLK];
__device__ unsigned g_count;      // zero-init at load; last block resets to 0

__global__ __launch_bounds__(THREADS)
void hncl_fused(const float* __restrict__ z1, const float* __restrict__ z2,
                float* __restrict__ out) {
    const int lane = threadIdx.x & 31;
    const int warp = threadIdx.x >> 5;                  // 0..31
    const int row  = blockIdx.x * NWARPS + warp;        // 0..8191

    // D=128 floats = 32 lanes x float4: two coalesced 512B loads per warp.
    const float4 a = reinterpret_cast<const float4*>(z1 + (size_t)row * DD)[lane];
    const float4 b = reinterpret_cast<const float4*>(z2 + (size_t)row * DD)[lane];

    float ss1 = a.x*a.x + a.y*a.y + a.z*a.z + a.w*a.w;
    float ss2 = b.x*b.x + b.y*b.y + b.z*b.z + b.w*b.w;
    float dp  = a.x*b.x + a.y*b.y + a.z*b.z + a.w*b.w;

    #pragma unroll
    for (int o = 16; o > 0; o >>= 1) {
        ss1 += __shfl_xor_sync(0xFFFFFFFFu, ss1, o);
        ss2 += __shfl_xor_sync(0xFFFFFFFFu, ss2, o);
        dp  += __shfl_xor_sync(0xFFFFFFFFu, dp,  o);
    }

    __shared__ float sacc[NWARPS];
    if (lane == 0) {
        const float n1 = fmaxf(sqrtf(ss1), 1e-12f);
        const float n2 = fmaxf(sqrtf(ss2), 1e-12f);
        sacc[warp] = fmaxf(10.5f - dp / (n1 * n2), 0.0f);
    }
    __syncthreads();

    // Warp 0 reduces the 32 warp-partials and runs the completion protocol.
    __shared__ unsigned s_is_last;
    if (warp == 0) {
        float v = sacc[lane];
        #pragma unroll
        for (int o = 16; o > 0; o >>= 1)
            v += __shfl_xor_sync(0xFFFFFFFFu, v, o);

        if (lane == 0) {
            g_partials[blockIdx.x] = v;
            __threadfence();                            // partial visible before count
            const unsigned done = atomicAdd(&g_count, 1u);
            s_is_last = (done == NBLK - 1) ? 1u : 0u;
        }
    }
    __syncthreads();

    if (s_is_last) {
        __shared__ float fin[8];
        if (threadIdx.x < NBLK) {
            // Last block reduces the 256 partials (deterministic order).
            float v = g_partials[threadIdx.x];
            #pragma unroll
            for (int o = 16; o > 0; o >>= 1)
                v += __shfl_xor_sync(0xFFFFFFFFu, v, o);
            if (lane == 0) fin[warp] = v;               // warps 0..7
        }
        __syncthreads();

        if (threadIdx.x == 0) {
            float s = 0.0f;
            #pragma unroll
            for (int w = 0; w < 8; w++) s += fin[w];
            out[0] = s * (1.0f / (float)BB);
            g_count = 0;                                // reset for next replay
        }
    }
}

extern "C" void kernel_launch(void* const* d_in, const int* in_sizes, int n_in,
                              void* d_out, int out_size) {
    const float* z1 = (const float*)d_in[0];
    const float* z2 = (const float*)d_in[1];
    float* out = (float*)d_out;
    (void)in_sizes; (void)n_in; (void)out_size;

    hncl_fused<<<NBLK, THREADS>>>(z1, z2, out);
}

// round 13
// speedup vs baseline: 1.2374x; 1.2374x over previous
#include <cuda_runtime.h>
#include <math.h>

// HardNegativeContrastiveLoss, B=8192, D=128, T=0.1, margin=0.5.
//
// Identity (R3): the reference leaves the diagonal of neg_sim unmasked, so
// hardest_neg[i] == 1/T exactly for any input. The O(B^2 D) GEMM vanishes:
//   loss = (1/B) * sum_i relu(10.5 - dot(z1_i,z2_i)/(||z1_i||*||z2_i||))
//
// R12: evidence says ~5us of the time is fixed launch/measurement floor and
// the work is ~2-3us. Shave the post-stream tail: carry each block's partial
// THROUGH a single 64-bit atomicAdd in fixed point (value<<16 | arrival=1).
// Integer adds are commutative -> bit-deterministic total, no threadfence,
// no partials array, no final 256-element re-reduce. Shape reverted to the
// best-measured R7 config (1024 blocks x 256 threads, one row per warp).

#define BB       8192
#define DD       128
#define THREADS  256
#define NWARPS   (THREADS / 32)
#define NBLK     1024                 // 1024 * 8 warps = 8192 rows
#define FIXSCALE 1048576.0f           // 2^20; max total ~86000*2^20 < 2^37 -> <<16 fits 2^53

__device__ unsigned long long g_acc;  // zero-init at load; finalizer resets to 0

__global__ __launch_bounds__(THREADS)
void hncl_fused(const float* __restrict__ z1, const float* __restrict__ z2,
                float* __restrict__ out) {
    const int lane = threadIdx.x & 31;
    const int warp = threadIdx.x >> 5;                  // 0..7
    const int row  = blockIdx.x * NWARPS + warp;        // 0..8191

    // D=128 floats = 32 lanes x float4: two coalesced 512B loads per warp.
    const float4 a = reinterpret_cast<const float4*>(z1 + (size_t)row * DD)[lane];
    const float4 b = reinterpret_cast<const float4*>(z2 + (size_t)row * DD)[lane];

    float ss1 = a.x*a.x + a.y*a.y + a.z*a.z + a.w*a.w;
    float ss2 = b.x*b.x + b.y*b.y + b.z*b.z + b.w*b.w;
    float dp  = a.x*b.x + a.y*b.y + a.z*b.z + a.w*b.w;

    #pragma unroll
    for (int o = 16; o > 0; o >>= 1) {
        ss1 += __shfl_xor_sync(0xFFFFFFFFu, ss1, o);
        ss2 += __shfl_xor_sync(0xFFFFFFFFu, ss2, o);
        dp  += __shfl_xor_sync(0xFFFFFFFFu, dp,  o);
    }

    __shared__ float sacc[NWARPS];
    if (lane == 0) {
        const float n1 = fmaxf(sqrtf(ss1), 1e-12f);
        const float n2 = fmaxf(sqrtf(ss2), 1e-12f);
        sacc[warp] = fmaxf(10.5f - dp / (n1 * n2), 0.0f);
    }
    __syncthreads();

    if (threadIdx.x == 0) {
        // Block partial in fixed order -> identical bits every run.
        float s = 0.0f;
        #pragma unroll
        for (int w = 0; w < NWARPS; w++) s += sacc[w];

        // Pack: high bits = fixed-point sum, low 16 bits = arrival count.
        const long long fx = __float2ll_rn(s * FIXSCALE);          // >= 0
        const unsigned long long contrib =
            ((unsigned long long)fx << 16) | 1ull;

        const unsigned long long oldv = atomicAdd(&g_acc, contrib);
        const unsigned long long newv = oldv + contrib;

        if ((newv & 0xFFFFull) == (unsigned long long)NBLK) {
            // This add completed the reduction; newv holds the full total.
            const double total = (double)(long long)(newv >> 16);
            out[0] = (float)(total / ((double)FIXSCALE * (double)BB));
            g_acc = 0ull;                                // reset for next replay
        }
    }
}

extern "C" void kernel_launch(void* const* d_in, const int* in_sizes, int n_in,
                              void* d_out, int out_size) {
    const float* z1 = (const float*)d_in[0];
    const float* z2 = (const float*)d_in[1];
    float* out = (float*)d_out;
    (void)in_sizes; (void)n_in; (void)out_size;

    hncl_fused<<<NBLK, THREADS>>>(z1, z2, out);
}

// round 14
// speedup vs baseline: 1.3092x; 1.0580x over previous
#include <cuda_runtime.h>
#include <math.h>

// HardNegativeContrastiveLoss, B=8192, D=128, T=0.1, margin=0.5.
//
// Identity (R3): the reference leaves the diagonal of neg_sim unmasked, so
// hardest_neg[i] == 1/T exactly for any input. The O(B^2 D) GEMM vanishes:
//   loss = (1/B) * sum_i relu(10.5 - dot(z1_i,z2_i)/(||z1_i||*||z2_i||))
//
// R13: R12's value-through-atomic tail worked (7.7->6.3 kernel). Now shave
// the convergence chain: 512 blocks (halves the same-address atomic train
// the completing block waits on), 2 rows/warp (same bytes-in-flight per SM),
// and __ldcs evict-first loads for the touch-once stream.

#define BB       8192
#define DD       128
#define THREADS  256
#define NWARPS   (THREADS / 32)
#define ROWS_PER_WARP 2
#define NBLK     512                  // 512 * 8 warps * 2 rows = 8192 rows
#define FIXSCALE 1048576.0f           // 2^20; total < 2^37, <<16 fits in 2^53

__device__ unsigned long long g_acc;  // zero-init at load; completer resets to 0

__global__ __launch_bounds__(THREADS)
void hncl_fused(const float* __restrict__ z1, const float* __restrict__ z2,
                float* __restrict__ out) {
    const int lane = threadIdx.x & 31;
    const int warp = threadIdx.x >> 5;                         // 0..7
    const int row0 = (blockIdx.x * NWARPS + warp) * ROWS_PER_WARP;

    // 4 independent coalesced 512B warp-loads in flight (evict-first stream).
    float4 a[ROWS_PER_WARP], b[ROWS_PER_WARP];
    #pragma unroll
    for (int k = 0; k < ROWS_PER_WARP; k++) {
        a[k] = __ldcs(reinterpret_cast<const float4*>(z1 + (size_t)(row0 + k) * DD) + lane);
        b[k] = __ldcs(reinterpret_cast<const float4*>(z2 + (size_t)(row0 + k) * DD) + lane);
    }

    float ss1[ROWS_PER_WARP], ss2[ROWS_PER_WARP], dp[ROWS_PER_WARP];
    #pragma unroll
    for (int k = 0; k < ROWS_PER_WARP; k++) {
        ss1[k] = a[k].x*a[k].x + a[k].y*a[k].y + a[k].z*a[k].z + a[k].w*a[k].w;
        ss2[k] = b[k].x*b[k].x + b[k].y*b[k].y + b[k].z*b[k].z + b[k].w*b[k].w;
        dp[k]  = a[k].x*b[k].x + a[k].y*b[k].y + a[k].z*b[k].z + a[k].w*b[k].w;
    }

    #pragma unroll
    for (int o = 16; o > 0; o >>= 1) {
        #pragma unroll
        for (int k = 0; k < ROWS_PER_WARP; k++) {
            ss1[k] += __shfl_xor_sync(0xFFFFFFFFu, ss1[k], o);
            ss2[k] += __shfl_xor_sync(0xFFFFFFFFu, ss2[k], o);
            dp[k]  += __shfl_xor_sync(0xFFFFFFFFu, dp[k],  o);
        }
    }

    __shared__ float sacc[NWARPS];
    if (lane == 0) {
        float s = 0.0f;
        #pragma unroll
        for (int k = 0; k < ROWS_PER_WARP; k++) {
            const float n1 = fmaxf(sqrtf(ss1[k]), 1e-12f);
            const float n2 = fmaxf(sqrtf(ss2[k]), 1e-12f);
            s += fmaxf(10.5f - dp[k] / (n1 * n2), 0.0f);
        }
        sacc[warp] = s;
    }
    __syncthreads();

    if (threadIdx.x == 0) {
        // Block partial in fixed order -> identical bits every run.
        float s = 0.0f;
        #pragma unroll
        for (int w = 0; w < NWARPS; w++) s += sacc[w];

        // Pack: high bits = fixed-point sum, low 16 bits = arrival count.
        // Integer adds commute -> order-independent, deterministic total.
        const long long fx = __float2ll_rn(s * FIXSCALE);      // >= 0
        const unsigned long long contrib =
            ((unsigned long long)fx << 16) | 1ull;

        const unsigned long long oldv = atomicAdd(&g_acc, contrib);
        const unsigned long long newv = oldv + contrib;

        if ((newv & 0xFFFFull) == (unsigned long long)NBLK) {
            // This add completed the reduction; newv holds the full total.
            const double total = (double)(long long)(newv >> 16);
            out[0] = (float)(total / ((double)FIXSCALE * (double)BB));
            g_acc = 0ull;                                       // reset for replay
        }
    }
}

extern "C" void kernel_launch(void* const* d_in, const int* in_sizes, int n_in,
                              void* d_out, int out_size) {
    const float* z1 = (const float*)d_in[0];
    const float* z2 = (const float*)d_in[1];
    float* out = (float*)d_out;
    (void)in_sizes; (void)n_in; (void)out_size;

    hncl_fused<<<NBLK, THREADS>>>(z1, z2, out);
}